// round 4
// baseline (speedup 1.0000x reference)
#include <cuda_runtime.h>

// GraphProposalNetwork, fp32, warp-per-batch.
// Key algebraic optimization: layer-1 (pair @ W1) factorizes into per-node
// projections u = feat@W1[:16] + b1, v = feat@W1[16:], so pre-activation of
// pair (i,j) is u[i] + v[j]. Cuts layer-1 MACs by ~20x per edge.

#define NN      10
#define FIN     3
#define FOUT    16
#define HID     32
#define H2      8
#define WARPS   8
#define THREADS (WARPS * 32)
#define USTRIDE 36   // padded row stride for u/v: 144B (16B aligned), banks (4*row+c)%32

__device__ __forceinline__ float lrelu(float x) {
    // leaky relu with slope 0.2 < 1:  max(x, 0.2x) == where(x>=0, x, 0.2x)
    return fmaxf(x, 0.2f * x);
}

__global__ __launch_bounds__(THREADS)
void gpn_kernel(const float* __restrict__ pos,   // [B,10,2]
                const float* __restrict__ ori,   // [B,10,1]
                const float* __restrict__ Wp,    // [3,16]
                const float* __restrict__ bp,    // [16]
                const float* __restrict__ W1,    // [32,32]
                const float* __restrict__ b1,    // [32]
                const float* __restrict__ W2,    // [32,8]
                const float* __restrict__ b2,    // [8]
                const float* __restrict__ W3,    // [8,2]
                const float* __restrict__ b3,    // [2]
                float* __restrict__ out_edge,    // [B,10,10,2]
                float* __restrict__ out_adj,     // [B,10,10] (as float), may be null
                int B)
{
    __shared__ __align__(16) float sWp[FIN * FOUT];
    __shared__ float sbp[FOUT];
    __shared__ __align__(16) float sW1[2 * FOUT * HID];
    __shared__ float sb1[HID];
    __shared__ __align__(16) float sW2[HID * H2];
    __shared__ float sb2[H2];
    __shared__ float sW3[H2 * 2];
    __shared__ float sb3[2];
    __shared__ float sIn[WARPS][NN][FIN];
    __shared__ __align__(16) float sF[WARPS][NN * FOUT];
    __shared__ __align__(16) float sU[WARPS][NN * USTRIDE];
    __shared__ __align__(16) float sV[WARPS][NN * USTRIDE];

    const int tid = threadIdx.x;

    // ---- stage weights to shared (block-cooperative) ----
    for (int t = tid; t < FIN * FOUT;     t += THREADS) sWp[t] = Wp[t];
    for (int t = tid; t < FOUT;           t += THREADS) sbp[t] = bp[t];
    for (int t = tid; t < 2 * FOUT * HID; t += THREADS) sW1[t] = W1[t];
    for (int t = tid; t < HID;            t += THREADS) sb1[t] = b1[t];
    for (int t = tid; t < HID * H2;       t += THREADS) sW2[t] = W2[t];
    for (int t = tid; t < H2;             t += THREADS) sb2[t] = b2[t];
    for (int t = tid; t < H2 * 2;         t += THREADS) sW3[t] = W3[t];
    for (int t = tid; t < 2;              t += THREADS) sb3[t] = b3[t];
    __syncthreads();

    const int w    = tid >> 5;
    const int lane = tid & 31;
    const int b    = blockIdx.x * WARPS + w;
    if (b >= B) return;

    // ---- load this batch's inputs (30 floats) ----
    if (lane < 2 * NN) {
        int n = lane >> 1, k = lane & 1;
        sIn[w][n][k] = pos[(size_t)b * (2 * NN) + lane];
    } else if (lane < 3 * NN) {
        int n = lane - 2 * NN;
        sIn[w][n][2] = ori[(size_t)b * NN + n];
    }
    __syncwarp();

    // ---- feat[n][c] = in[n][:] @ Wp + bp  (160 outputs, 5 per lane) ----
    #pragma unroll
    for (int q = 0; q < 5; ++q) {
        int t = lane + 32 * q;
        int n = t >> 4, c = t & 15;
        float a = sbp[c];
        a += sIn[w][n][0] * sWp[0 * FOUT + c];
        a += sIn[w][n][1] * sWp[1 * FOUT + c];
        a += sIn[w][n][2] * sWp[2 * FOUT + c];
        sF[w][n * FOUT + c] = a;
    }
    __syncwarp();

    // ---- u[n][c] = feat[n] @ W1[:16,:] + b1 ;  v[n][c] = feat[n] @ W1[16:,:]
    // lane = output channel c (0..31)
    {
        const int c = lane;
        #pragma unroll
        for (int n = 0; n < NN; ++n) {
            const float4* fv = (const float4*)&sF[w][n * FOUT];
            float4 f0 = fv[0], f1 = fv[1], f2 = fv[2], f3 = fv[3];
            float fr[16] = { f0.x, f0.y, f0.z, f0.w,
                             f1.x, f1.y, f1.z, f1.w,
                             f2.x, f2.y, f2.z, f2.w,
                             f3.x, f3.y, f3.z, f3.w };
            float u = sb1[c];
            float v = 0.f;
            #pragma unroll
            for (int k = 0; k < 16; ++k) {
                u += fr[k] * sW1[k * HID + c];
                v += fr[k] * sW1[(16 + k) * HID + c];
            }
            sU[w][n * USTRIDE + c] = u;
            sV[w][n * USTRIDE + c] = v;
        }
    }
    __syncwarp();

    // ---- per-warp register copies of tiny tail weights ----
    float b2r[H2], w30[H2], w31[H2];
    #pragma unroll
    for (int m = 0; m < H2; ++m) {
        b2r[m] = sb2[m];
        w30[m] = sW3[2 * m];
        w31[m] = sW3[2 * m + 1];
    }
    const float b30 = sb3[0], b31 = sb3[1];

    const float4* w2v   = (const float4*)sW2;
    float2*       edge2 = (float2*)out_edge + (size_t)b * (NN * NN);
    float*        adjp  = out_adj ? out_adj + (size_t)b * (NN * NN) : (float*)0;

    // ---- pair phase: 100 pairs, lane = pair, 4 rounds ----
    #pragma unroll
    for (int r = 0; r < 4; ++r) {
        int p = r * 32 + lane;
        if (p < NN * NN) {
            int i  = p / 10;
            int jj = p - i * 10;
            // idx[i,0]=i ; idx[i,1:] = all j != i in order
            int j = (jj == 0) ? i : ((jj <= i) ? jj - 1 : jj);

            // h1 = lrelu(u[i] + v[j])   (b1 folded into u)
            float h1[HID];
            const float4* uv = (const float4*)&sU[w][i * USTRIDE];
            const float4* vv = (const float4*)&sV[w][j * USTRIDE];
            #pragma unroll
            for (int q = 0; q < 8; ++q) {
                float4 ua = uv[q];
                float4 va = vv[q];
                h1[4 * q + 0] = lrelu(ua.x + va.x);
                h1[4 * q + 1] = lrelu(ua.y + va.y);
                h1[4 * q + 2] = lrelu(ua.z + va.z);
                h1[4 * q + 3] = lrelu(ua.w + va.w);
            }

            // layer 2: acc = h1 @ W2 + b2
            float acc[H2];
            #pragma unroll
            for (int m = 0; m < H2; ++m) acc[m] = b2r[m];
            #pragma unroll
            for (int c = 0; c < HID; ++c) {
                float4 wa = w2v[2 * c];
                float4 wb = w2v[2 * c + 1];
                float  hc = h1[c];
                acc[0] += hc * wa.x; acc[1] += hc * wa.y;
                acc[2] += hc * wa.z; acc[3] += hc * wa.w;
                acc[4] += hc * wb.x; acc[5] += hc * wb.y;
                acc[6] += hc * wb.z; acc[7] += hc * wb.w;
            }

            // layer 3: e = lrelu(acc) @ W3 + b3 ; adjacency = argmax(e)
            float e0 = b30, e1 = b31;
            #pragma unroll
            for (int m = 0; m < H2; ++m) {
                float h2 = lrelu(acc[m]);
                e0 += h2 * w30[m];
                e1 += h2 * w31[m];
            }

            edge2[p] = make_float2(e0, e1);
            if (adjp) adjp[p] = (e1 > e0) ? 1.0f : 0.0f;
        }
    }
}

extern "C" void kernel_launch(void* const* d_in, const int* in_sizes, int n_in,
                              void* d_out, int out_size)
{
    const float* pos = (const float*)d_in[0];
    const float* ori = (const float*)d_in[1];
    const float* Wp  = (const float*)d_in[2];
    const float* bp  = (const float*)d_in[3];
    const float* W1  = (const float*)d_in[4];
    const float* b1  = (const float*)d_in[5];
    const float* W2  = (const float*)d_in[6];
    const float* b2  = (const float*)d_in[7];
    const float* W3  = (const float*)d_in[8];
    const float* b3  = (const float*)d_in[9];

    const int B = in_sizes[0] / (2 * NN);   // position is [B,10,2]

    float* out      = (float*)d_out;
    float* out_edge = out;                                   // B*100*2 floats
    // adjacency segment only if the output buffer actually holds it
    float* out_adj  = ((size_t)out_size >= (size_t)B * 300)
                        ? out + (size_t)B * 200 : (float*)0;

    const int blocks = (B + WARPS - 1) / WARPS;
    gpn_kernel<<<blocks, THREADS>>>(pos, ori, Wp, bp, W1, b1, W2, b2, W3, b3,
                                    out_edge, out_adj, B);
}